// round 1
// baseline (speedup 1.0000x reference)
#include <cuda_runtime.h>
#include <cuda_bf16.h>
#include <cstdint>

// Problem constants
#define B_  8
#define T_  2048
#define C_  1024
#define H_  64
#define M_  (B_ * T_)          // 16384 rows of x

// Scratch for projected q, k, v (4 MB each) — __device__ globals (no allocs allowed)
__device__ float g_q[M_ * H_];
__device__ float g_k[M_ * H_];
__device__ float g_v[M_ * H_];

// ---------------------------------------------------------------------------
// Kernel 1: fused QKV projection.  out[w] = x @ W[w], W in {Wq, Wk, Wv}.
// Grid: M/64 blocks, 256 threads. Each block computes a 64-row slab for all
// three weights (x tile read once from HBM). 4x4 register blocking per thread.
// ---------------------------------------------------------------------------
#define PBK 32

__global__ __launch_bounds__(256) void proj_kernel(
    const float* __restrict__ x,
    const float* __restrict__ Wq,
    const float* __restrict__ Wk,
    const float* __restrict__ Wv)
{
    __shared__ float  Xs[64][PBK + 1];          // padded: conflict-free column reads
    __shared__ float4 Ws4[3][PBK][16];          // 3 weights, PBK x 64 floats each

    const int tid = threadIdx.x;
    const int tr  = tid >> 4;   // 0..15 -> rows tr*4..tr*4+3
    const int tc  = tid & 15;   // 0..15 -> cols tc*4..tc*4+3
    const int m0  = blockIdx.x * 64;

    float acc0[16], acc1[16], acc2[16];
#pragma unroll
    for (int i = 0; i < 16; i++) { acc0[i] = 0.f; acc1[i] = 0.f; acc2[i] = 0.f; }

    for (int kk = 0; kk < C_; kk += PBK) {
        // load X tile 64 x PBK (float4 from gmem, scalar stores into padded smem)
        for (int i = tid; i < 64 * (PBK / 4); i += 256) {
            int r = i >> 3, cq = i & 7;
            float4 v = ((const float4*)(x + (size_t)(m0 + r) * C_ + kk))[cq];
            Xs[r][cq * 4 + 0] = v.x;
            Xs[r][cq * 4 + 1] = v.y;
            Xs[r][cq * 4 + 2] = v.z;
            Xs[r][cq * 4 + 3] = v.w;
        }
        // load W tiles (PBK x 64 each, 3 of them)
        for (int i = tid; i < 3 * PBK * 16; i += 256) {
            int w = i / (PBK * 16), rem = i % (PBK * 16);
            int r = rem >> 4, cq = rem & 15;
            const float* Wp = (w == 0) ? Wq : (w == 1) ? Wk : Wv;
            Ws4[w][r][cq] = ((const float4*)(Wp + (size_t)(kk + r) * H_))[cq];
        }
        __syncthreads();

#pragma unroll 8
        for (int d = 0; d < PBK; d++) {
            float xr[4];
#pragma unroll
            for (int i = 0; i < 4; i++) xr[i] = Xs[tr * 4 + i][d];
            float4 wq = Ws4[0][d][tc];
            float4 wk = Ws4[1][d][tc];
            float4 wv = Ws4[2][d][tc];
#pragma unroll
            for (int i = 0; i < 4; i++) {
                acc0[i*4+0] += xr[i]*wq.x; acc0[i*4+1] += xr[i]*wq.y;
                acc0[i*4+2] += xr[i]*wq.z; acc0[i*4+3] += xr[i]*wq.w;
                acc1[i*4+0] += xr[i]*wk.x; acc1[i*4+1] += xr[i]*wk.y;
                acc1[i*4+2] += xr[i]*wk.z; acc1[i*4+3] += xr[i]*wk.w;
                acc2[i*4+0] += xr[i]*wv.x; acc2[i*4+1] += xr[i]*wv.y;
                acc2[i*4+2] += xr[i]*wv.z; acc2[i*4+3] += xr[i]*wv.w;
            }
        }
        __syncthreads();
    }

#pragma unroll
    for (int i = 0; i < 4; i++) {
        size_t off = (size_t)(m0 + tr * 4 + i) * H_ + tc * 4;
        float4 oq = make_float4(acc0[i*4+0], acc0[i*4+1], acc0[i*4+2], acc0[i*4+3]);
        float4 ok = make_float4(acc1[i*4+0], acc1[i*4+1], acc1[i*4+2], acc1[i*4+3]);
        float4 ov = make_float4(acc2[i*4+0], acc2[i*4+1], acc2[i*4+2], acc2[i*4+3]);
        *(float4*)(g_q + off) = oq;
        *(float4*)(g_k + off) = ok;
        *(float4*)(g_v + off) = ov;
    }
}

// ---------------------------------------------------------------------------
// Kernel 2: causal flash attention, fp32.
// Grid: (T/64, B). Block = 256 threads. Br = Bc = 64.
// Each thread owns a 4x4 tile of S and of O (tr = row group, tc = col group).
// Online softmax: 4 threads per row with shfl reductions.
// ---------------------------------------------------------------------------
#define QROW 68   // padded row stride (floats) for Q/K/V tiles (16B-aligned)
#define SROW 65   // padded row stride for S tile

__global__ __launch_bounds__(256) void attn_kernel(float* __restrict__ out)
{
    extern __shared__ float sm[];
    float* Qs   = sm;                      // 64*68
    float* Ks   = Qs + 64 * QROW;          // 64*68
    float* Vs   = Ks + 64 * QROW;          // 64*68
    float* Ssm  = Vs + 64 * QROW;          // 64*65
    float* mrow = Ssm + 64 * SROW;         // 64
    float* lrow = mrow + 64;               // 64
    float* srow = lrow + 64;               // 64

    const int qt  = blockIdx.x;
    const int b   = blockIdx.y;
    const int tid = threadIdx.x;
    const int tr  = tid >> 4;              // 0..15
    const int tc  = tid & 15;              // 0..15
    const size_t base = (size_t)b * T_ * H_;

    // load Q tile (64 x 64)
    for (int i = tid; i < 64 * 16; i += 256) {
        int r = i >> 4, cq = i & 15;
        float4 v = ((const float4*)(g_q + base + (size_t)(qt * 64 + r) * H_))[cq];
        *(float4*)(Qs + r * QROW + cq * 4) = v;
    }
    if (tid < 64) { mrow[tid] = -1e30f; lrow[tid] = 0.f; }

    float acc[4][4];
#pragma unroll
    for (int i = 0; i < 4; i++)
#pragma unroll
        for (int j = 0; j < 4; j++) acc[i][j] = 0.f;

    for (int st = 0; st <= qt; st++) {
        __syncthreads();   // Q ready (first iter) / previous PV done reading Ks,Vs,Ssm

        // load K and V tiles (64 x 64 each)
        for (int i = tid; i < 64 * 16; i += 256) {
            int r = i >> 4, cq = i & 15;
            size_t roff = base + (size_t)(st * 64 + r) * H_;
            *(float4*)(Ks + r * QROW + cq * 4) = ((const float4*)(g_k + roff))[cq];
            *(float4*)(Vs + r * QROW + cq * 4) = ((const float4*)(g_v + roff))[cq];
        }
        __syncthreads();

        // S = Q K^T (4x4 per thread, float4 over d)
        float s[4][4];
#pragma unroll
        for (int i = 0; i < 4; i++)
#pragma unroll
            for (int j = 0; j < 4; j++) s[i][j] = 0.f;

#pragma unroll 4
        for (int d4 = 0; d4 < 16; d4++) {
            float4 qv[4], kv[4];
#pragma unroll
            for (int i = 0; i < 4; i++)
                qv[i] = *(const float4*)(Qs + (tr * 4 + i) * QROW + d4 * 4);
#pragma unroll
            for (int j = 0; j < 4; j++)
                kv[j] = *(const float4*)(Ks + (tc * 4 + j) * QROW + d4 * 4);
#pragma unroll
            for (int i = 0; i < 4; i++)
#pragma unroll
                for (int j = 0; j < 4; j++)
                    s[i][j] += qv[i].x * kv[j].x + qv[i].y * kv[j].y
                             + qv[i].z * kv[j].z + qv[i].w * kv[j].w;
        }

        const bool diag = (st == qt);
#pragma unroll
        for (int i = 0; i < 4; i++) {
#pragma unroll
            for (int j = 0; j < 4; j++) {
                float val = s[i][j] * 0.125f;   // * H^-0.5
                if (diag && (tc * 4 + j > tr * 4 + i)) val = -1e30f;
                Ssm[(tr * 4 + i) * SROW + tc * 4 + j] = val;
            }
        }
        __syncthreads();

        // online softmax: 4 threads per row
        {
            int r = tid >> 2, sl = tid & 3;
            float mold = mrow[r];
            float mx = mold;
            for (int c = sl; c < 64; c += 4) mx = fmaxf(mx, Ssm[r * SROW + c]);
            mx = fmaxf(mx, __shfl_xor_sync(0xffffffffu, mx, 1));
            mx = fmaxf(mx, __shfl_xor_sync(0xffffffffu, mx, 2));
            float sum = 0.f;
            for (int c = sl; c < 64; c += 4) {
                float p = __expf(Ssm[r * SROW + c] - mx);
                Ssm[r * SROW + c] = p;
                sum += p;
            }
            sum += __shfl_xor_sync(0xffffffffu, sum, 1);
            sum += __shfl_xor_sync(0xffffffffu, sum, 2);
            if (sl == 0) {
                float scv = __expf(mold - mx);
                srow[r] = scv;
                lrow[r] = lrow[r] * scv + sum;
                mrow[r] = mx;
            }
        }
        __syncthreads();

        // rescale O and accumulate O += P @ V
#pragma unroll
        for (int i = 0; i < 4; i++) {
            float scv = srow[tr * 4 + i];
#pragma unroll
            for (int j = 0; j < 4; j++) acc[i][j] *= scv;
        }
#pragma unroll 8
        for (int ss = 0; ss < 64; ss++) {
            float4 vv = *(const float4*)(Vs + ss * QROW + tc * 4);
#pragma unroll
            for (int i = 0; i < 4; i++) {
                float p = Ssm[(tr * 4 + i) * SROW + ss];
                acc[i][0] += p * vv.x;
                acc[i][1] += p * vv.y;
                acc[i][2] += p * vv.z;
                acc[i][3] += p * vv.w;
            }
        }
    }

    // epilogue: divide by l, write out
#pragma unroll
    for (int i = 0; i < 4; i++) {
        int r = tr * 4 + i;
        float inv = 1.f / lrow[r];
        float4 o = make_float4(acc[i][0] * inv, acc[i][1] * inv,
                               acc[i][2] * inv, acc[i][3] * inv);
        *(float4*)(out + base + (size_t)(qt * 64 + r) * H_ + tc * 4) = o;
    }
}

// ---------------------------------------------------------------------------
// Launcher. Inputs (metadata order): x, Wk, Wq, Wv. Output: [B,T,H] fp32.
// ---------------------------------------------------------------------------
extern "C" void kernel_launch(void* const* d_in, const int* in_sizes, int n_in,
                              void* d_out, int out_size)
{
    const float* x  = (const float*)d_in[0];
    const float* Wk = (const float*)d_in[1];
    const float* Wq = (const float*)d_in[2];
    const float* Wv = (const float*)d_in[3];
    float* out = (float*)d_out;

    static const int ATTN_SMEM = (3 * 64 * QROW + 64 * SROW + 3 * 64) * (int)sizeof(float);
    cudaFuncSetAttribute(attn_kernel, cudaFuncAttributeMaxDynamicSharedMemorySize, ATTN_SMEM);

    proj_kernel<<<M_ / 64, 256>>>(x, Wq, Wk, Wv);
    attn_kernel<<<dim3(T_ / 64, B_), 256, ATTN_SMEM>>>(out);
}

// round 2
// speedup vs baseline: 1.0021x; 1.0021x over previous
#include <cuda_runtime.h>
#include <cuda_bf16.h>
#include <cstdint>

// Problem constants
#define B_  8
#define T_  2048
#define C_  1024
#define H_  64
#define M_  (B_ * T_)          // 16384 rows of x

// Scratch for projected q, k, v (4 MB each) — __device__ globals (no allocs allowed)
__device__ float g_q[M_ * H_];
__device__ float g_k[M_ * H_];
__device__ float g_v[M_ * H_];

// ---------------------------------------------------------------------------
// Kernel 1: fused QKV projection.  out[w] = x @ W[w], W in {Wq, Wk, Wv}.
// Grid: M/64 blocks, 256 threads. Each block computes a 64-row slab for all
// three weights (x tile read once from HBM). 4x4 register blocking per thread.
// ---------------------------------------------------------------------------
#define PBK 32

__global__ __launch_bounds__(256) void proj_kernel(
    const float* __restrict__ x,
    const float* __restrict__ Wq,
    const float* __restrict__ Wk,
    const float* __restrict__ Wv)
{
    __shared__ float  Xs[64][PBK + 1];          // padded: conflict-free column reads
    __shared__ float4 Ws4[3][PBK][16];          // 3 weights, PBK x 64 floats each

    const int tid = threadIdx.x;
    const int tr  = tid >> 4;   // 0..15 -> rows tr*4..tr*4+3
    const int tc  = tid & 15;   // 0..15 -> cols tc*4..tc*4+3
    const int m0  = blockIdx.x * 64;

    float acc0[16], acc1[16], acc2[16];
#pragma unroll
    for (int i = 0; i < 16; i++) { acc0[i] = 0.f; acc1[i] = 0.f; acc2[i] = 0.f; }

    for (int kk = 0; kk < C_; kk += PBK) {
        // load X tile 64 x PBK (float4 from gmem, scalar stores into padded smem)
        for (int i = tid; i < 64 * (PBK / 4); i += 256) {
            int r = i >> 3, cq = i & 7;
            float4 v = ((const float4*)(x + (size_t)(m0 + r) * C_ + kk))[cq];
            Xs[r][cq * 4 + 0] = v.x;
            Xs[r][cq * 4 + 1] = v.y;
            Xs[r][cq * 4 + 2] = v.z;
            Xs[r][cq * 4 + 3] = v.w;
        }
        // load W tiles (PBK x 64 each, 3 of them)
        for (int i = tid; i < 3 * PBK * 16; i += 256) {
            int w = i / (PBK * 16), rem = i % (PBK * 16);
            int r = rem >> 4, cq = rem & 15;
            const float* Wp = (w == 0) ? Wq : (w == 1) ? Wk : Wv;
            Ws4[w][r][cq] = ((const float4*)(Wp + (size_t)(kk + r) * H_))[cq];
        }
        __syncthreads();

#pragma unroll 8
        for (int d = 0; d < PBK; d++) {
            float xr[4];
#pragma unroll
            for (int i = 0; i < 4; i++) xr[i] = Xs[tr * 4 + i][d];
            float4 wq = Ws4[0][d][tc];
            float4 wk = Ws4[1][d][tc];
            float4 wv = Ws4[2][d][tc];
#pragma unroll
            for (int i = 0; i < 4; i++) {
                acc0[i*4+0] += xr[i]*wq.x; acc0[i*4+1] += xr[i]*wq.y;
                acc0[i*4+2] += xr[i]*wq.z; acc0[i*4+3] += xr[i]*wq.w;
                acc1[i*4+0] += xr[i]*wk.x; acc1[i*4+1] += xr[i]*wk.y;
                acc1[i*4+2] += xr[i]*wk.z; acc1[i*4+3] += xr[i]*wk.w;
                acc2[i*4+0] += xr[i]*wv.x; acc2[i*4+1] += xr[i]*wv.y;
                acc2[i*4+2] += xr[i]*wv.z; acc2[i*4+3] += xr[i]*wv.w;
            }
        }
        __syncthreads();
    }

#pragma unroll
    for (int i = 0; i < 4; i++) {
        size_t off = (size_t)(m0 + tr * 4 + i) * H_ + tc * 4;
        float4 oq = make_float4(acc0[i*4+0], acc0[i*4+1], acc0[i*4+2], acc0[i*4+3]);
        float4 ok = make_float4(acc1[i*4+0], acc1[i*4+1], acc1[i*4+2], acc1[i*4+3]);
        float4 ov = make_float4(acc2[i*4+0], acc2[i*4+1], acc2[i*4+2], acc2[i*4+3]);
        *(float4*)(g_q + off) = oq;
        *(float4*)(g_k + off) = ok;
        *(float4*)(g_v + off) = ov;
    }
}

// ---------------------------------------------------------------------------
// Kernel 2: causal flash attention, fp32.
// Grid: (T/64, B). Block = 256 threads. Br = Bc = 64.
// Each thread owns a 4x4 tile of S and of O (tr = row group, tc = col group).
// Online softmax: 4 threads per row with shfl reductions.
// ---------------------------------------------------------------------------
#define QROW 68   // padded row stride (floats) for Q/K/V tiles (16B-aligned)
#define SROW 65   // padded row stride for S tile

__global__ __launch_bounds__(256) void attn_kernel(float* __restrict__ out)
{
    extern __shared__ float sm[];
    float* Qs   = sm;                      // 64*68
    float* Ks   = Qs + 64 * QROW;          // 64*68
    float* Vs   = Ks + 64 * QROW;          // 64*68
    float* Ssm  = Vs + 64 * QROW;          // 64*65
    float* mrow = Ssm + 64 * SROW;         // 64
    float* lrow = mrow + 64;               // 64
    float* srow = lrow + 64;               // 64

    const int qt  = blockIdx.x;
    const int b   = blockIdx.y;
    const int tid = threadIdx.x;
    const int tr  = tid >> 4;              // 0..15
    const int tc  = tid & 15;              // 0..15
    const size_t base = (size_t)b * T_ * H_;

    // load Q tile (64 x 64)
    for (int i = tid; i < 64 * 16; i += 256) {
        int r = i >> 4, cq = i & 15;
        float4 v = ((const float4*)(g_q + base + (size_t)(qt * 64 + r) * H_))[cq];
        *(float4*)(Qs + r * QROW + cq * 4) = v;
    }
    if (tid < 64) { mrow[tid] = -1e30f; lrow[tid] = 0.f; }

    float acc[4][4];
#pragma unroll
    for (int i = 0; i < 4; i++)
#pragma unroll
        for (int j = 0; j < 4; j++) acc[i][j] = 0.f;

    for (int st = 0; st <= qt; st++) {
        __syncthreads();   // Q ready (first iter) / previous PV done reading Ks,Vs,Ssm

        // load K and V tiles (64 x 64 each)
        for (int i = tid; i < 64 * 16; i += 256) {
            int r = i >> 4, cq = i & 15;
            size_t roff = base + (size_t)(st * 64 + r) * H_;
            *(float4*)(Ks + r * QROW + cq * 4) = ((const float4*)(g_k + roff))[cq];
            *(float4*)(Vs + r * QROW + cq * 4) = ((const float4*)(g_v + roff))[cq];
        }
        __syncthreads();

        // S = Q K^T (4x4 per thread, float4 over d)
        float s[4][4];
#pragma unroll
        for (int i = 0; i < 4; i++)
#pragma unroll
            for (int j = 0; j < 4; j++) s[i][j] = 0.f;

#pragma unroll 4
        for (int d4 = 0; d4 < 16; d4++) {
            float4 qv[4], kv[4];
#pragma unroll
            for (int i = 0; i < 4; i++)
                qv[i] = *(const float4*)(Qs + (tr * 4 + i) * QROW + d4 * 4);
#pragma unroll
            for (int j = 0; j < 4; j++)
                kv[j] = *(const float4*)(Ks + (tc * 4 + j) * QROW + d4 * 4);
#pragma unroll
            for (int i = 0; i < 4; i++)
#pragma unroll
                for (int j = 0; j < 4; j++)
                    s[i][j] += qv[i].x * kv[j].x + qv[i].y * kv[j].y
                             + qv[i].z * kv[j].z + qv[i].w * kv[j].w;
        }

        const bool diag = (st == qt);
#pragma unroll
        for (int i = 0; i < 4; i++) {
#pragma unroll
            for (int j = 0; j < 4; j++) {
                float val = s[i][j] * 0.125f;   // * H^-0.5
                if (diag && (tc * 4 + j > tr * 4 + i)) val = -1e30f;
                Ssm[(tr * 4 + i) * SROW + tc * 4 + j] = val;
            }
        }
        __syncthreads();

        // online softmax: 4 threads per row
        {
            int r = tid >> 2, sl = tid & 3;
            float mold = mrow[r];
            float mx = mold;
            for (int c = sl; c < 64; c += 4) mx = fmaxf(mx, Ssm[r * SROW + c]);
            mx = fmaxf(mx, __shfl_xor_sync(0xffffffffu, mx, 1));
            mx = fmaxf(mx, __shfl_xor_sync(0xffffffffu, mx, 2));
            float sum = 0.f;
            for (int c = sl; c < 64; c += 4) {
                float p = __expf(Ssm[r * SROW + c] - mx);
                Ssm[r * SROW + c] = p;
                sum += p;
            }
            sum += __shfl_xor_sync(0xffffffffu, sum, 1);
            sum += __shfl_xor_sync(0xffffffffu, sum, 2);
            if (sl == 0) {
                float scv = __expf(mold - mx);
                srow[r] = scv;
                lrow[r] = lrow[r] * scv + sum;
                mrow[r] = mx;
            }
        }
        __syncthreads();

        // rescale O and accumulate O += P @ V
#pragma unroll
        for (int i = 0; i < 4; i++) {
            float scv = srow[tr * 4 + i];
#pragma unroll
            for (int j = 0; j < 4; j++) acc[i][j] *= scv;
        }
#pragma unroll 8
        for (int ss = 0; ss < 64; ss++) {
            float4 vv = *(const float4*)(Vs + ss * QROW + tc * 4);
#pragma unroll
            for (int i = 0; i < 4; i++) {
                float p = Ssm[(tr * 4 + i) * SROW + ss];
                acc[i][0] += p * vv.x;
                acc[i][1] += p * vv.y;
                acc[i][2] += p * vv.z;
                acc[i][3] += p * vv.w;
            }
        }
    }

    // epilogue: divide by l, write out
#pragma unroll
    for (int i = 0; i < 4; i++) {
        int r = tr * 4 + i;
        float inv = 1.f / lrow[r];
        float4 o = make_float4(acc[i][0] * inv, acc[i][1] * inv,
                               acc[i][2] * inv, acc[i][3] * inv);
        *(float4*)(out + base + (size_t)(qt * 64 + r) * H_ + tc * 4) = o;
    }
}

// ---------------------------------------------------------------------------
// Launcher. Inputs (metadata order): x, Wk, Wq, Wv. Output: [B,T,H] fp32.
// ---------------------------------------------------------------------------
extern "C" void kernel_launch(void* const* d_in, const int* in_sizes, int n_in,
                              void* d_out, int out_size)
{
    const float* x  = (const float*)d_in[0];
    const float* Wk = (const float*)d_in[1];
    const float* Wq = (const float*)d_in[2];
    const float* Wv = (const float*)d_in[3];
    float* out = (float*)d_out;

    static const int ATTN_SMEM = (3 * 64 * QROW + 64 * SROW + 3 * 64) * (int)sizeof(float);
    cudaFuncSetAttribute(attn_kernel, cudaFuncAttributeMaxDynamicSharedMemorySize, ATTN_SMEM);

    proj_kernel<<<M_ / 64, 256>>>(x, Wq, Wk, Wv);
    attn_kernel<<<dim3(T_ / 64, B_), 256, ATTN_SMEM>>>(out);
}

// round 3
// speedup vs baseline: 1.0028x; 1.0007x over previous
#include <cuda_runtime.h>
#include <cuda_bf16.h>
#include <cstdint>

// Problem constants
#define B_  8
#define T_  2048
#define C_  1024
#define H_  64
#define M_  (B_ * T_)          // 16384 rows of x

// Scratch for projected q, k, v (4 MB each) — __device__ globals (no allocs allowed)
__device__ float g_q[M_ * H_];
__device__ float g_k[M_ * H_];
__device__ float g_v[M_ * H_];

// ---------------------------------------------------------------------------
// Kernel 1: fused QKV projection.  out[w] = x @ W[w], W in {Wq, Wk, Wv}.
// Grid: M/64 blocks, 256 threads. Each block computes a 64-row slab for all
// three weights (x tile read once from HBM). 4x4 register blocking per thread.
// ---------------------------------------------------------------------------
#define PBK 32

__global__ __launch_bounds__(256) void proj_kernel(
    const float* __restrict__ x,
    const float* __restrict__ Wq,
    const float* __restrict__ Wk,
    const float* __restrict__ Wv)
{
    __shared__ float  Xs[64][PBK + 1];          // padded: conflict-free column reads
    __shared__ float4 Ws4[3][PBK][16];          // 3 weights, PBK x 64 floats each

    const int tid = threadIdx.x;
    const int tr  = tid >> 4;   // 0..15 -> rows tr*4..tr*4+3
    const int tc  = tid & 15;   // 0..15 -> cols tc*4..tc*4+3
    const int m0  = blockIdx.x * 64;

    float acc0[16], acc1[16], acc2[16];
#pragma unroll
    for (int i = 0; i < 16; i++) { acc0[i] = 0.f; acc1[i] = 0.f; acc2[i] = 0.f; }

    for (int kk = 0; kk < C_; kk += PBK) {
        // load X tile 64 x PBK (float4 from gmem, scalar stores into padded smem)
        for (int i = tid; i < 64 * (PBK / 4); i += 256) {
            int r = i >> 3, cq = i & 7;
            float4 v = ((const float4*)(x + (size_t)(m0 + r) * C_ + kk))[cq];
            Xs[r][cq * 4 + 0] = v.x;
            Xs[r][cq * 4 + 1] = v.y;
            Xs[r][cq * 4 + 2] = v.z;
            Xs[r][cq * 4 + 3] = v.w;
        }
        // load W tiles (PBK x 64 each, 3 of them)
        for (int i = tid; i < 3 * PBK * 16; i += 256) {
            int w = i / (PBK * 16), rem = i % (PBK * 16);
            int r = rem >> 4, cq = rem & 15;
            const float* Wp = (w == 0) ? Wq : (w == 1) ? Wk : Wv;
            Ws4[w][r][cq] = ((const float4*)(Wp + (size_t)(kk + r) * H_))[cq];
        }
        __syncthreads();

#pragma unroll 8
        for (int d = 0; d < PBK; d++) {
            float xr[4];
#pragma unroll
            for (int i = 0; i < 4; i++) xr[i] = Xs[tr * 4 + i][d];
            float4 wq = Ws4[0][d][tc];
            float4 wk = Ws4[1][d][tc];
            float4 wv = Ws4[2][d][tc];
#pragma unroll
            for (int i = 0; i < 4; i++) {
                acc0[i*4+0] += xr[i]*wq.x; acc0[i*4+1] += xr[i]*wq.y;
                acc0[i*4+2] += xr[i]*wq.z; acc0[i*4+3] += xr[i]*wq.w;
                acc1[i*4+0] += xr[i]*wk.x; acc1[i*4+1] += xr[i]*wk.y;
                acc1[i*4+2] += xr[i]*wk.z; acc1[i*4+3] += xr[i]*wk.w;
                acc2[i*4+0] += xr[i]*wv.x; acc2[i*4+1] += xr[i]*wv.y;
                acc2[i*4+2] += xr[i]*wv.z; acc2[i*4+3] += xr[i]*wv.w;
            }
        }
        __syncthreads();
    }

#pragma unroll
    for (int i = 0; i < 4; i++) {
        size_t off = (size_t)(m0 + tr * 4 + i) * H_ + tc * 4;
        float4 oq = make_float4(acc0[i*4+0], acc0[i*4+1], acc0[i*4+2], acc0[i*4+3]);
        float4 ok = make_float4(acc1[i*4+0], acc1[i*4+1], acc1[i*4+2], acc1[i*4+3]);
        float4 ov = make_float4(acc2[i*4+0], acc2[i*4+1], acc2[i*4+2], acc2[i*4+3]);
        *(float4*)(g_q + off) = oq;
        *(float4*)(g_k + off) = ok;
        *(float4*)(g_v + off) = ov;
    }
}

// ---------------------------------------------------------------------------
// Kernel 2: causal flash attention, fp32.
// Grid: (T/64, B). Block = 256 threads. Br = Bc = 64.
// Each thread owns a 4x4 tile of S and of O (tr = row group, tc = col group).
// Online softmax: 4 threads per row with shfl reductions.
// ---------------------------------------------------------------------------
#define QROW 68   // padded row stride (floats) for Q/K/V tiles (16B-aligned)
#define SROW 65   // padded row stride for S tile

__global__ __launch_bounds__(256) void attn_kernel(float* __restrict__ out)
{
    extern __shared__ float sm[];
    float* Qs   = sm;                      // 64*68
    float* Ks   = Qs + 64 * QROW;          // 64*68
    float* Vs   = Ks + 64 * QROW;          // 64*68
    float* Ssm  = Vs + 64 * QROW;          // 64*65
    float* mrow = Ssm + 64 * SROW;         // 64
    float* lrow = mrow + 64;               // 64
    float* srow = lrow + 64;               // 64

    const int qt  = blockIdx.x;
    const int b   = blockIdx.y;
    const int tid = threadIdx.x;
    const int tr  = tid >> 4;              // 0..15
    const int tc  = tid & 15;              // 0..15
    const size_t base = (size_t)b * T_ * H_;

    // load Q tile (64 x 64)
    for (int i = tid; i < 64 * 16; i += 256) {
        int r = i >> 4, cq = i & 15;
        float4 v = ((const float4*)(g_q + base + (size_t)(qt * 64 + r) * H_))[cq];
        *(float4*)(Qs + r * QROW + cq * 4) = v;
    }
    if (tid < 64) { mrow[tid] = -1e30f; lrow[tid] = 0.f; }

    float acc[4][4];
#pragma unroll
    for (int i = 0; i < 4; i++)
#pragma unroll
        for (int j = 0; j < 4; j++) acc[i][j] = 0.f;

    for (int st = 0; st <= qt; st++) {
        __syncthreads();   // Q ready (first iter) / previous PV done reading Ks,Vs,Ssm

        // load K and V tiles (64 x 64 each)
        for (int i = tid; i < 64 * 16; i += 256) {
            int r = i >> 4, cq = i & 15;
            size_t roff = base + (size_t)(st * 64 + r) * H_;
            *(float4*)(Ks + r * QROW + cq * 4) = ((const float4*)(g_k + roff))[cq];
            *(float4*)(Vs + r * QROW + cq * 4) = ((const float4*)(g_v + roff))[cq];
        }
        __syncthreads();

        // S = Q K^T (4x4 per thread, float4 over d)
        float s[4][4];
#pragma unroll
        for (int i = 0; i < 4; i++)
#pragma unroll
            for (int j = 0; j < 4; j++) s[i][j] = 0.f;

#pragma unroll 4
        for (int d4 = 0; d4 < 16; d4++) {
            float4 qv[4], kv[4];
#pragma unroll
            for (int i = 0; i < 4; i++)
                qv[i] = *(const float4*)(Qs + (tr * 4 + i) * QROW + d4 * 4);
#pragma unroll
            for (int j = 0; j < 4; j++)
                kv[j] = *(const float4*)(Ks + (tc * 4 + j) * QROW + d4 * 4);
#pragma unroll
            for (int i = 0; i < 4; i++)
#pragma unroll
                for (int j = 0; j < 4; j++)
                    s[i][j] += qv[i].x * kv[j].x + qv[i].y * kv[j].y
                             + qv[i].z * kv[j].z + qv[i].w * kv[j].w;
        }

        const bool diag = (st == qt);
#pragma unroll
        for (int i = 0; i < 4; i++) {
#pragma unroll
            for (int j = 0; j < 4; j++) {
                float val = s[i][j] * 0.125f;   // * H^-0.5
                if (diag && (tc * 4 + j > tr * 4 + i)) val = -1e30f;
                Ssm[(tr * 4 + i) * SROW + tc * 4 + j] = val;
            }
        }
        __syncthreads();

        // online softmax: 4 threads per row
        {
            int r = tid >> 2, sl = tid & 3;
            float mold = mrow[r];
            float mx = mold;
            for (int c = sl; c < 64; c += 4) mx = fmaxf(mx, Ssm[r * SROW + c]);
            mx = fmaxf(mx, __shfl_xor_sync(0xffffffffu, mx, 1));
            mx = fmaxf(mx, __shfl_xor_sync(0xffffffffu, mx, 2));
            float sum = 0.f;
            for (int c = sl; c < 64; c += 4) {
                float p = __expf(Ssm[r * SROW + c] - mx);
                Ssm[r * SROW + c] = p;
                sum += p;
            }
            sum += __shfl_xor_sync(0xffffffffu, sum, 1);
            sum += __shfl_xor_sync(0xffffffffu, sum, 2);
            if (sl == 0) {
                float scv = __expf(mold - mx);
                srow[r] = scv;
                lrow[r] = lrow[r] * scv + sum;
                mrow[r] = mx;
            }
        }
        __syncthreads();

        // rescale O and accumulate O += P @ V
#pragma unroll
        for (int i = 0; i < 4; i++) {
            float scv = srow[tr * 4 + i];
#pragma unroll
            for (int j = 0; j < 4; j++) acc[i][j] *= scv;
        }
#pragma unroll 8
        for (int ss = 0; ss < 64; ss++) {
            float4 vv = *(const float4*)(Vs + ss * QROW + tc * 4);
#pragma unroll
            for (int i = 0; i < 4; i++) {
                float p = Ssm[(tr * 4 + i) * SROW + ss];
                acc[i][0] += p * vv.x;
                acc[i][1] += p * vv.y;
                acc[i][2] += p * vv.z;
                acc[i][3] += p * vv.w;
            }
        }
    }

    // epilogue: divide by l, write out
#pragma unroll
    for (int i = 0; i < 4; i++) {
        int r = tr * 4 + i;
        float inv = 1.f / lrow[r];
        float4 o = make_float4(acc[i][0] * inv, acc[i][1] * inv,
                               acc[i][2] * inv, acc[i][3] * inv);
        *(float4*)(out + base + (size_t)(qt * 64 + r) * H_ + tc * 4) = o;
    }
}

// ---------------------------------------------------------------------------
// Launcher. Inputs (metadata order): x, Wk, Wq, Wv. Output: [B,T,H] fp32.
// ---------------------------------------------------------------------------
extern "C" void kernel_launch(void* const* d_in, const int* in_sizes, int n_in,
                              void* d_out, int out_size)
{
    const float* x  = (const float*)d_in[0];
    const float* Wk = (const float*)d_in[1];
    const float* Wq = (const float*)d_in[2];
    const float* Wv = (const float*)d_in[3];
    float* out = (float*)d_out;

    static const int ATTN_SMEM = (3 * 64 * QROW + 64 * SROW + 3 * 64) * (int)sizeof(float);
    cudaFuncSetAttribute(attn_kernel, cudaFuncAttributeMaxDynamicSharedMemorySize, ATTN_SMEM);

    proj_kernel<<<M_ / 64, 256>>>(x, Wq, Wk, Wv);
    attn_kernel<<<dim3(T_ / 64, B_), 256, ATTN_SMEM>>>(out);
}